// round 17
// baseline (speedup 1.0000x reference)
#include <cuda_runtime.h>
#include <math.h>
#include <stdint.h>

#define EB 262144
#define MP 786432
#define FNB 192
#define DM 256
#define KT 448
#define NST 28            // 448 / 16 k-stages
#define SA 20             // A smem row stride (words)
#define SB 20             // B smem row stride (words)

// ---- scratch ----
__device__ float g_s[(size_t)EB * DM];
__device__ float g_r[(size_t)EB * DM];
__device__ float g_z[(size_t)EB * DM];
// pre-converted/transposed/permuted weights: [mat][stage][n=256][16]
__device__ uint32_t g_Bw[(size_t)3 * NST * 256 * 16];

// ---------------- helpers ----------------
__device__ __forceinline__ uint32_t smem_u32(const void* p) {
    uint32_t a;
    asm("{ .reg .u64 t; cvta.to.shared.u64 t, %1; cvt.u32.u64 %0, t; }" : "=r"(a) : "l"(p));
    return a;
}
__device__ __forceinline__ uint32_t to_tf32(float f) {
    uint32_t r;
    asm("cvt.rna.tf32.f32 %0, %1;" : "=r"(r) : "f"(f));
    return r;
}
__device__ __forceinline__ void red4(float* p, float a, float b, float c, float d) {
    asm volatile("red.global.add.v4.f32 [%0], {%1,%2,%3,%4};"
                 :: "l"(p), "f"(a), "f"(b), "f"(c), "f"(d) : "memory");
}
__device__ __forceinline__ void cpasync16(uint32_t dst, const void* src) {
    asm volatile("cp.async.cg.shared.global [%0], [%1], 16;" :: "r"(dst), "l"(src) : "memory");
}
#define CP_COMMIT() asm volatile("cp.async.commit_group;" ::: "memory")

__device__ __forceinline__ float sigmoidf_(float x) { return 1.f / (1.f + __expf(-x)); }

#define MMA8(d, a0, a1, a2, a3, b0, b1)                                         \
    asm volatile("mma.sync.aligned.m16n8k8.row.col.f32.tf32.tf32.f32 "          \
                 "{%0,%1,%2,%3}, {%4,%5,%6,%7}, {%8,%9}, {%0,%1,%2,%3};"        \
                 : "+f"((d)[0]), "+f"((d)[1]), "+f"((d)[2]), "+f"((d)[3])       \
                 : "r"(a0), "r"(a1), "r"(a2), "r"(a3), "r"(b0), "r"(b1))

__global__ void zero_scratch() {
    size_t n4 = ((size_t)EB * DM) / 4;
    float4 z = make_float4(0.f, 0.f, 0.f, 0.f);
    for (size_t i = (size_t)blockIdx.x * blockDim.x + threadIdx.x; i < n4;
         i += (size_t)gridDim.x * blockDim.x) {
        reinterpret_cast<float4*>(g_s)[i] = z;
        reinterpret_cast<float4*>(g_r)[i] = z;
    }
}

// weights -> tf32, transposed to [n][k], k permuted within each 16-chunk:
// pos = (k&3)*4 + (k>>2); layout g_Bw[((mat*NST+s)*256 + n)*16 + pos]
__global__ void prep_w(const float* __restrict__ Wz_w, const float* __restrict__ Wr_w,
                       const float* __restrict__ U_w,  const float* __restrict__ W_w) {
    int k = blockIdx.x, mat = blockIdx.y, n = threadIdx.x;
    float v;
    if (mat == 0)      v = Wr_w[(size_t)k * DM + n];
    else if (mat == 1) v = Wz_w[(size_t)k * DM + n];
    else               v = (k < FNB) ? W_w[(size_t)k * DM + n]
                                     : U_w[(size_t)(k - FNB) * DM + n];
    int s = k >> 4, kk = k & 15;
    int pos = (kk & 3) * 4 + (kk >> 2);
    g_Bw[((size_t)(mat * NST + s) * 256 + n) * 16 + pos] = to_tf32(v);
}

// MODE 0: pairs  A=[h_ki | mess[nei]] @ Wr ; epi: sigmoid, v4-red(r*mess -> g_r[src]);
//                plus v4-red(mess -> g_s[src]) pre-pass
// MODE 1: bonds  A=[h_ij | g_s] @ Wz ; epi: g_z = sigmoid
// MODE 2: bonds  A=[h_ij | g_r] @ [W;U] ; epi: out = (1-z)*s + z*tanh
template <int MODE>
__global__ __launch_bounds__(256, 2)
void dmpnn_mma(const float* __restrict__ h_ij, const float* __restrict__ h_ki,
               const float* __restrict__ mess,
               const int* __restrict__ src_idx, const int* __restrict__ nei_idx,
               const float* __restrict__ Wz_b, const float* __restrict__ Wr_b,
               const float* __restrict__ W_b, float* __restrict__ out)
{
    __shared__ uint32_t As2[2][128 * SA];   // permuted tf32 A tiles
    __shared__ uint32_t Bs2[2][128 * SB];   // permuted tf32 B tiles
    __shared__ int s_src[128], s_nei[128];

    const int tid  = threadIdx.x;
    const int warp = tid >> 5;
    const int lane = tid & 31;
    const int wr   = warp & 3;          // warp row (4)
    const int wc   = warp >> 2;         // warp col (2)
    const int gid  = lane >> 2;         // 0..7
    const int tig  = lane & 3;          // 0..3
    const int r0   = blockIdx.x * 128;
    const int n0   = blockIdx.y * 128;

    if (MODE == 0 && tid < 128) {
        s_src[tid] = src_idx[r0 + tid];
        s_nei[tid] = nei_idx[r0 + tid];
    }
    __syncthreads();

    const uint32_t bSm[2] = { smem_u32(&Bs2[0][0]), smem_u32(&Bs2[1][0]) };

    // A fill assignment: thread -> row = tid>>1, khalf = tid&1 (k = kh*8 + j*4 + i)
    const int arow = tid >> 1;
    const int akh  = tid & 1;

    // returns the global pointer for this thread's A row at k-offset k0+akh*8
    auto aptr = [&](int s) -> const float* {
        const int k0 = s * 16 + akh * 8;
        if (MODE == 0)
            return (k0 < FNB) ? h_ki + (size_t)(r0 + arow) * FNB + k0
                              : mess + (size_t)s_nei[arow] * DM + (k0 - FNB);
        else if (MODE == 1)
            return (k0 < FNB) ? h_ij + (size_t)(r0 + arow) * FNB + k0
                              : g_s + (size_t)(r0 + arow) * DM + (k0 - FNB);
        else
            return (k0 < FNB) ? h_ij + (size_t)(r0 + arow) * FNB + k0
                              : g_r + (size_t)(r0 + arow) * DM + (k0 - FNB);
    };

    float4 pf0, pf1;        // prefetch regs: k = akh*8 + {0..3}, {4..7}
    auto ldgA = [&](int s) {
        const float* p = aptr(s);
        pf0 = *(const float4*)(p);
        pf1 = *(const float4*)(p + 4);
    };
    // store prefetched A into stage buffer st, cvt + permuted (4x STS.64)
    auto stsA = [&](int st) {
        uint32_t* dst = &As2[st][arow * SA + akh * 2];
        uint2 w;
        w.x = to_tf32(pf0.x); w.y = to_tf32(pf1.x); *(uint2*)(dst + 0)  = w;
        w.x = to_tf32(pf0.y); w.y = to_tf32(pf1.y); *(uint2*)(dst + 4)  = w;
        w.x = to_tf32(pf0.z); w.y = to_tf32(pf1.z); *(uint2*)(dst + 8)  = w;
        w.x = to_tf32(pf0.w); w.y = to_tf32(pf1.w); *(uint2*)(dst + 12) = w;
    };
    const uint32_t* bsrc_base =
        g_Bw + ((size_t)((MODE == 0 ? 0 : (MODE == 1 ? 1 : 2)) * NST) * 256 + n0) * 16;
    auto fillB = [&](int s) {
        const int st = s & 1;
        const uint32_t* src = bsrc_base + (size_t)s * 256 * 16;
        // 128 rows x 16 words = 2048 words = 8 x 16B per thread
#pragma unroll
        for (int i = 0; i < 2; ++i) {
            int idx = tid + 256 * i;          // 0..511 -> (row, 16B-chunk 0..3)
            int row = idx >> 2, c = idx & 3;
            cpasync16(bSm[st] + (row * SB + c * 4) * 4, src + row * 16 + c * 4);
        }
        CP_COMMIT();
    };

    float acc[2][8][4];
#pragma unroll
    for (int mt = 0; mt < 2; ++mt)
#pragma unroll
        for (int nt = 0; nt < 8; ++nt)
#pragma unroll
            for (int q = 0; q < 4; ++q) acc[mt][nt][q] = 0.f;

    // ---- preamble ----
    ldgA(0);
    fillB(0);
    stsA(0);
    ldgA(1);

    if (MODE == 0) {
        // s_ij scatter for cols [n0, n0+128) — overlaps fill latency
        for (int it = tid; it < 128 * 32; it += 256) {
            int row = it >> 5, c = (it & 31) << 2;
            const float4 v = *(const float4*)(mess + (size_t)s_nei[row] * DM + n0 + c);
            red4(g_s + (size_t)s_src[row] * DM + n0 + c, v.x, v.y, v.z, v.w);
        }
    }

#pragma unroll 1
    for (int s = 0; s < NST; ++s) {
        const int st = s & 1;
        if (s + 1 < NST) {
            stsA(st ^ 1);
            fillB(s + 1);
            asm volatile("cp.async.wait_group 1;" ::: "memory");
        } else {
            asm volatile("cp.async.wait_group 0;" ::: "memory");
        }
        if (s + 2 < NST) ldgA(s + 2);
        __syncthreads();

        // ---- compute stage s: 12 LDS.128 + 32 MMA ----
        uint4 a0[2], a1[2];
#pragma unroll
        for (int mt = 0; mt < 2; ++mt) {
            const int rb = wr * 32 + mt * 16;
            a0[mt] = *(const uint4*)&As2[st][(rb + gid) * SA + tig * 4];
            a1[mt] = *(const uint4*)&As2[st][(rb + gid + 8) * SA + tig * 4];
        }
#pragma unroll
        for (int nt = 0; nt < 8; ++nt) {
            const uint4 b = *(const uint4*)&Bs2[st][(wc * 64 + nt * 8 + gid) * SB + tig * 4];
#pragma unroll
            for (int mt = 0; mt < 2; ++mt) {
                MMA8(acc[mt][nt], a0[mt].x, a1[mt].x, a0[mt].y, a1[mt].y, b.x, b.y);
                MMA8(acc[mt][nt], a0[mt].z, a1[mt].z, a0[mt].w, a1[mt].w, b.z, b.w);
            }
        }
        __syncthreads();
    }

    // ---- epilogue ----
#pragma unroll
    for (int mt = 0; mt < 2; ++mt) {
#pragma unroll
        for (int half = 0; half < 2; ++half) {
            const int lr = wr * 32 + mt * 16 + gid + half * 8;  // local row
            const int gm = r0 + lr;
            if (MODE == 0) {
                const float* mrow = mess + (size_t)s_nei[lr] * DM;
                float* rdst = g_r + (size_t)s_src[lr] * DM;
#pragma unroll
                for (int nt = 0; nt < 8; ++nt) {
                    const int n = n0 + wc * 64 + nt * 8 + 2 * tig;
                    float v0 = acc[mt][nt][half * 2 + 0];
                    float v1 = acc[mt][nt][half * 2 + 1];
                    float2 bb = *(const float2*)(Wr_b + n);
                    float2 m2 = *(const float2*)(mrow + n);
                    float p0 = sigmoidf_(v0 + bb.x) * m2.x;
                    float p1 = sigmoidf_(v1 + bb.y) * m2.y;
                    float q0 = __shfl_down_sync(0xffffffffu, p0, 1);
                    float q1 = __shfl_down_sync(0xffffffffu, p1, 1);
                    if ((tig & 1) == 0)
                        red4(rdst + n, p0, p1, q0, q1);
                }
            } else if (MODE == 1) {
#pragma unroll
                for (int nt = 0; nt < 8; ++nt) {
                    const int n = n0 + wc * 64 + nt * 8 + 2 * tig;
                    float2 bb = *(const float2*)(Wz_b + n);
                    float2 zz;
                    zz.x = sigmoidf_(acc[mt][nt][half * 2 + 0] + bb.x);
                    zz.y = sigmoidf_(acc[mt][nt][half * 2 + 1] + bb.y);
                    *(float2*)(g_z + (size_t)gm * DM + n) = zz;
                }
            } else {
#pragma unroll
                for (int nt = 0; nt < 8; ++nt) {
                    const int n = n0 + wc * 64 + nt * 8 + 2 * tig;
                    float2 bb = *(const float2*)(W_b + n);
                    float2 z2 = *(const float2*)(g_z + (size_t)gm * DM + n);
                    float2 s2 = *(const float2*)(g_s + (size_t)gm * DM + n);
                    float2 o;
                    o.x = (1.f - z2.x) * s2.x +
                          z2.x * tanhf(acc[mt][nt][half * 2 + 0] + bb.x);
                    o.y = (1.f - z2.y) * s2.y +
                          z2.y * tanhf(acc[mt][nt][half * 2 + 1] + bb.y);
                    *(float2*)(out + (size_t)gm * DM + n) = o;
                }
            }
        }
    }
}

// ---------------- launch ----------------
extern "C" void kernel_launch(void* const* d_in, const int* in_sizes, int n_in,
                              void* d_out, int out_size) {
    const float* h_ij = (const float*)d_in[0];
    const float* h_ki = (const float*)d_in[1];
    const float* mess = (const float*)d_in[2];
    const int* src_i  = (const int*)d_in[3];
    const int* nei_i  = (const int*)d_in[4];
    const float* Wz_w = (const float*)d_in[5];
    const float* Wz_b = (const float*)d_in[6];
    const float* Wr_w = (const float*)d_in[7];
    const float* Wr_b = (const float*)d_in[8];
    const float* U_w  = (const float*)d_in[9];
    const float* W_w  = (const float*)d_in[10];
    const float* W_b  = (const float*)d_in[11];
    float* out = (float*)d_out;

    zero_scratch<<<1184, 256>>>();
    prep_w<<<dim3(KT, 3), 256>>>(Wz_w, Wr_w, U_w, W_w);

    dim3 g0(MP / 128, 2);
    dmpnn_mma<0><<<g0, 256>>>(h_ij, h_ki, mess, src_i, nei_i,
                              Wz_b, Wr_b, W_b, out);
    dim3 g1(EB / 128, 2);
    dmpnn_mma<1><<<g1, 256>>>(h_ij, h_ki, mess, src_i, nei_i,
                              Wz_b, Wr_b, W_b, out);
    dmpnn_mma<2><<<g1, 256>>>(h_ij, h_ki, mess, src_i, nei_i,
                              Wz_b, Wr_b, W_b, out);
}